// round 2
// baseline (speedup 1.0000x reference)
#include <cuda_runtime.h>
#include <math.h>

#define B   16
#define CI  64
#define CO  64
#define H   256
#define W   256
#define MH  8
#define MW  12
#define NC  24            // 12 re + 12 im per row
#define S1  (1.0f/256.0f) // forward ortho norm
#define S2  (1.0f/256.0f) // inverse ortho norm

// ---------- device scratch (static, no allocation) ----------
__device__ float d_ctab[MW*W];   // cos(2*pi*ky*w/256)
__device__ float d_stab[MW*W];   // sin(2*pi*ky*w/256)
__device__ float d_hc[MH*H];     // cos(2*pi*kx*h/256)
__device__ float d_hs[MH*H];     // sin(2*pi*kx*h/256)
__device__ float d_T[(size_t)B*CI*H*NC];     // 25.2 MB: [bc][h][24]
__device__ float d_X[(size_t)B*96*CI*2];     // [b][mode][i][2]
__device__ float d_Y[(size_t)B*CO*96*2];     // [b][o][mode][2]
__device__ float d_wT[(size_t)96*CI*CO*2];   // [mode][i][o][2]

// ---------- trig tables ----------
__global__ void init_trig() {
    int idx = blockIdx.x * blockDim.x + threadIdx.x;
    if (idx < 3072) {               // 12 ky x 256 w
        int ky = idx >> 8, w = idx & 255;
        double a = 2.0 * (double)ky * (double)w / 256.0;
        double s, c; sincospi(a, &s, &c);
        d_ctab[idx] = (float)c; d_stab[idx] = (float)s;
    } else if (idx < 5120) {        // 8 kx x 256 h
        int j = idx - 3072;
        int kx = j >> 8, h = j & 255;
        double a = 2.0 * (double)kx * (double)h / 256.0;
        double s, c; sincospi(a, &s, &c);
        d_hc[j] = (float)c; d_hs[j] = (float)s;
    }
}

// ---------- weight transpose: [i][o][m][2] -> [m][i][o][2] ----------
__global__ void __launch_bounds__(64) transpose_w(const float* __restrict__ wsrc) {
    int m = blockIdx.x;   // 0..95
    int o = threadIdx.x;  // 0..63
    const float2* src = (const float2*)wsrc;
    float2* dst = (float2*)d_wT;
    #pragma unroll 4
    for (int i = 0; i < CI; ++i) {
        dst[(m*CI + i)*CO + o] = src[(size_t)(i*CO + o)*96 + m];
    }
}

// ---------- K1: forward row DFT ----------
// T[bc][h][ky]    = S1 * sum_w x[h][w]*cos
// T[bc][h][12+ky] = -S1 * sum_w x[h][w]*sin     (e^{-i theta})
__global__ void __launch_bounds__(256) k1_fwd_row(const float* __restrict__ x) {
    extern __shared__ float sm[];
    float* sct = sm;            // 3072
    float* sst = sm + 3072;     // 3072
    float* sx  = sm + 6144;     // 64 rows x 260 (padded)

    int bc = blockIdx.y;
    int h0 = blockIdx.x * 64;
    int t  = threadIdx.x;

    for (int i = t; i < 3072; i += 256) { sct[i] = d_ctab[i]; sst[i] = d_stab[i]; }

    const float* xb = x + ((size_t)bc*H + h0)*W;
    for (int i = t; i < 4096; i += 256) {
        int r = i >> 6, wq = i & 63;
        float4 v = ((const float4*)(xb + (size_t)r*W))[wq];
        *((float4*)(sx + r*260 + wq*4)) = v;
    }
    __syncthreads();

    int rp = t >> 3;        // 0..31 row pair
    int qc = t & 7;         // 0..7 w-phase
    int r0 = rp*2, r1 = r0 + 1;

    float aC0[12], aS0[12], aC1[12], aS1[12];
    #pragma unroll
    for (int k = 0; k < 12; ++k) { aC0[k]=0.f; aS0[k]=0.f; aC1[k]=0.f; aS1[k]=0.f; }

    const float* px0 = sx + r0*260 + qc;
    const float* px1 = sx + r1*260 + qc;

    #pragma unroll 4
    for (int j = 0; j < 32; ++j) {
        int w = qc + 8*j;
        float x0 = px0[8*j];
        float x1 = px1[8*j];
        #pragma unroll
        for (int ky = 0; ky < 12; ++ky) {
            float c = sct[ky*256 + w];
            float s = sst[ky*256 + w];
            aC0[ky] += x0*c; aS0[ky] += x0*s;
            aC1[ky] += x1*c; aS1[ky] += x1*s;
        }
    }

    // reduce across qc (lane bits 0..2)
    #pragma unroll
    for (int k = 0; k < 12; ++k) {
        float v;
        v = aC0[k]; v += __shfl_xor_sync(0xffffffffu, v, 1); v += __shfl_xor_sync(0xffffffffu, v, 2); v += __shfl_xor_sync(0xffffffffu, v, 4); aC0[k] = v;
        v = aS0[k]; v += __shfl_xor_sync(0xffffffffu, v, 1); v += __shfl_xor_sync(0xffffffffu, v, 2); v += __shfl_xor_sync(0xffffffffu, v, 4); aS0[k] = v;
        v = aC1[k]; v += __shfl_xor_sync(0xffffffffu, v, 1); v += __shfl_xor_sync(0xffffffffu, v, 2); v += __shfl_xor_sync(0xffffffffu, v, 4); aC1[k] = v;
        v = aS1[k]; v += __shfl_xor_sync(0xffffffffu, v, 1); v += __shfl_xor_sync(0xffffffffu, v, 2); v += __shfl_xor_sync(0xffffffffu, v, 4); aS1[k] = v;
    }

    if (qc == 0) {
        float* T0 = d_T + ((size_t)bc*H + h0 + r0)*NC;
        float* T1 = d_T + ((size_t)bc*H + h0 + r1)*NC;
        #pragma unroll
        for (int k = 0; k < 12; ++k) {
            T0[k]    =  S1*aC0[k];
            T0[12+k] = -S1*aS0[k];
            T1[k]    =  S1*aC1[k];
            T1[12+k] = -S1*aS1[k];
        }
    }
}

// ---------- K2: forward column DFT (contract h -> kx) ----------
// X[mode] = sum_h T[h] * e^{-i phi}:  Xre = sum(Tre*c + Tim*s); Xim = sum(Tim*c - Tre*s)
__global__ void __launch_bounds__(128) k2_fwd_col() {
    __shared__ float sT2[H*NC];          // 24 KB
    __shared__ float shc[MH*260];        // padded
    __shared__ float shs[MH*260];

    int bc = blockIdx.x;
    int t  = threadIdx.x;

    for (int i = t; i < H*NC; i += 128) sT2[i] = d_T[(size_t)bc*H*NC + i];
    for (int i = t; i < MH*H; i += 128) {
        int kx = i >> 8, h = i & 255;
        shc[kx*260 + h] = d_hc[i];
        shs[kx*260 + h] = d_hs[i];
    }
    __syncthreads();

    if (t < 96) {
        int kx = t / 12, ky = t % 12;
        float xr = 0.f, xi = 0.f;
        #pragma unroll 4
        for (int h = 0; h < H; ++h) {
            float tre = sT2[h*NC + ky];
            float tim = sT2[h*NC + 12 + ky];
            float c = shc[kx*260 + h];
            float s = shs[kx*260 + h];
            xr += tre*c + tim*s;
            xi += tim*c - tre*s;
        }
        int b = bc >> 6, ci = bc & 63;
        ((float2*)d_X)[(size_t)(b*96 + t)*CI + ci] = make_float2(xr, xi);
    }
}

// ---------- K3: per-mode channel mixing ----------
__global__ void __launch_bounds__(64) k3_mix() {
    __shared__ float2 sXm[CI];
    int m = blockIdx.x;   // 0..95
    int b = blockIdx.y;   // 0..15
    int o = threadIdx.x;  // 0..63

    const float2* Xp = (const float2*)d_X + (size_t)(b*96 + m)*CI;
    sXm[o] = Xp[o];
    __syncthreads();

    float yr = 0.f, yi = 0.f;
    const float2* wp = (const float2*)d_wT + (size_t)m*CI*CO + o;
    #pragma unroll 8
    for (int i = 0; i < CI; ++i) {
        float2 xv = sXm[i];
        float2 wv = wp[(size_t)i*CO];
        yr += xv.x*wv.x - xv.y*wv.y;
        yi += xv.x*wv.y + xv.y*wv.x;
    }
    ((float2*)d_Y)[(size_t)(b*CO + o)*96 + m] = make_float2(yr, yi);
}

// ---------- K45: inverse column ifft (coeffs) + inverse row synthesis ----------
// G[h][ky] = sum_kx Y[kx][ky]*e^{+i phi}
// out[h][w] = S2*( ReG[h][0] + 2*sum_{ky>=1}(ReG cos - ImG sin) )
__global__ void __launch_bounds__(256) k45_inv(float* __restrict__ out) {
    __shared__ float sY[192];
    __shared__ float shc[MH*260];
    __shared__ float shs[MH*260];
    __shared__ __align__(16) float sC[256*28];  // [h][24] padded to 28

    int bo = blockIdx.x;     // b*CO + o
    int t  = threadIdx.x;    // doubles as h (coef phase) and w (main phase)

    for (int i = t; i < 192;   i += 256) sY[i] = d_Y[(size_t)bo*192 + i];
    for (int i = t; i < MH*H;  i += 256) {
        int kx = i >> 8, h = i & 255;
        shc[kx*260 + h] = d_hc[i];
        shs[kx*260 + h] = d_hs[i];
    }
    float cr[12], sr[12];
    #pragma unroll
    for (int ky = 0; ky < 12; ++ky) {
        cr[ky] = d_ctab[ky*256 + t];
        sr[ky] = d_stab[ky*256 + t];
    }
    __syncthreads();

    // coefficients for h = t
    {
        float gre[12], gim[12];
        #pragma unroll
        for (int ky = 0; ky < 12; ++ky) { gre[ky]=0.f; gim[ky]=0.f; }
        #pragma unroll
        for (int kx = 0; kx < MH; ++kx) {
            float c = shc[kx*260 + t];
            float s = shs[kx*260 + t];
            #pragma unroll
            for (int ky = 0; ky < 12; ++ky) {
                float yr = sY[(kx*12 + ky)*2];
                float yi = sY[(kx*12 + ky)*2 + 1];
                gre[ky] += yr*c - yi*s;
                gim[ky] += yr*s + yi*c;
            }
        }
        sC[t*28 + 0] = S2*gre[0];
        #pragma unroll
        for (int ky = 1; ky < 12; ++ky) sC[t*28 + ky] = 2.f*S2*gre[ky];
        #pragma unroll
        for (int ky = 0; ky < 12; ++ky) sC[t*28 + 12 + ky] = -2.f*S2*gim[ky];
    }
    __syncthreads();

    float* op = out + (size_t)bo*H*W + t;
    #pragma unroll 2
    for (int h = 0; h < H; ++h) {
        const float4* p = (const float4*)(sC + h*28);
        float4 a0 = p[0], a1 = p[1], a2 = p[2];
        float4 b0 = p[3], b1 = p[4], b2 = p[5];
        float acc;
        acc  = a0.x*cr[0]  + a0.y*cr[1]  + a0.z*cr[2]  + a0.w*cr[3];
        acc += a1.x*cr[4]  + a1.y*cr[5]  + a1.z*cr[6]  + a1.w*cr[7];
        acc += a2.x*cr[8]  + a2.y*cr[9]  + a2.z*cr[10] + a2.w*cr[11];
        acc += b0.x*sr[0]  + b0.y*sr[1]  + b0.z*sr[2]  + b0.w*sr[3];
        acc += b1.x*sr[4]  + b1.y*sr[5]  + b1.z*sr[6]  + b1.w*sr[7];
        acc += b2.x*sr[8]  + b2.y*sr[9]  + b2.z*sr[10] + b2.w*sr[11];
        op[(size_t)h*W] = acc;
    }
}

// ---------- launch ----------
extern "C" void kernel_launch(void* const* d_in, const int* in_sizes, int n_in,
                              void* d_out, int out_size) {
    const float* x = (const float*)d_in[0];
    const float* w = (const float*)d_in[1];
    float* out = (float*)d_out;

    cudaFuncSetAttribute(k1_fwd_row, cudaFuncAttributeMaxDynamicSharedMemorySize, 91136);

    init_trig<<<20, 256>>>();
    transpose_w<<<96, 64>>>(w);
    k1_fwd_row<<<dim3(4, B*CI), 256, 91136>>>(x);
    k2_fwd_col<<<B*CI, 128>>>();
    k3_mix<<<dim3(96, B), 64>>>();
    k45_inv<<<B*CO, 256>>>(out);
}